// round 9
// baseline (speedup 1.0000x reference)
#include <cuda_runtime.h>
#include <cstdint>

typedef unsigned long long ull;

#define NB 512
#define NT 512
#define NC 64
#define WPB 2              // warps per CTA; each warp owns TWO batches
#define THREADS (32 * WPB) // grid = 128 CTAs -> 256 warps -> 512 batches
#define FULLMASK 0xffffffffu
#define LN2F 0.6931471805599453f

__device__ float    g_partial[NB];
__device__ unsigned g_done;   // self-resetting completion counter

static __device__ __forceinline__ ull fma2(ull a, ull b, ull c) {
    ull d; asm("fma.rn.f32x2 %0,%1,%2,%3;" : "=l"(d) : "l"(a), "l"(b), "l"(c)); return d;
}
static __device__ __forceinline__ ull add2(ull a, ull b) {
    ull d; asm("add.rn.f32x2 %0,%1,%2;" : "=l"(d) : "l"(a), "l"(b)); return d;
}
static __device__ __forceinline__ ull pack2(float x, float y) {
    ull d; asm("mov.b64 %0,{%1,%2};" : "=l"(d) : "f"(x), "f"(y)); return d;
}
static __device__ __forceinline__ void unpack2(ull v, float& x, float& y) {
    asm("mov.b64 {%0,%1},%2;" : "=f"(x), "=f"(y) : "l"(v));
}

// One forward step for TWO independent batches, interleaved so each chain's
// stall slots are filled by the partner chain. e2 (exp of transitions) is
// shared. Static in/out buffers (ping-pong chosen at the call site).
// Renorm: exact power-of-2 rescale, no rcp/log in the hot loop.
#define STEP2(PIN0, POUT0, PIN1, POUT1, EM0, M0, EM1, M1, REN) do {              \
    float ex0_ = __expf((EM0).x), ey0_ = __expf((EM0).y);                        \
    float ex1_ = __expf((EM1).x), ey1_ = __expf((EM1).y);                        \
    const ulonglong2* pa_ = (const ulonglong2*)(PIN0);                           \
    const ulonglong2* pb_ = (const ulonglong2*)(PIN1);                           \
    ull qa0_=0, qa1_=0, qa2_=0, qa3_=0;                                          \
    ull qb0_=0, qb1_=0, qb2_=0, qb3_=0;                                          \
    _Pragma("unroll")                                                            \
    for (int g_ = 0; g_ < 32; g_ += 2) {                                         \
        ulonglong2 va0_ = pa_[g_];                                               \
        ulonglong2 vb0_ = pb_[g_];                                               \
        ulonglong2 va1_ = pa_[g_ + 1];                                           \
        ulonglong2 vb1_ = pb_[g_ + 1];                                           \
        qa0_ = fma2(va0_.x, e2[2*g_ + 0], qa0_);                                 \
        qb0_ = fma2(vb0_.x, e2[2*g_ + 0], qb0_);                                 \
        qa1_ = fma2(va0_.y, e2[2*g_ + 1], qa1_);                                 \
        qb1_ = fma2(vb0_.y, e2[2*g_ + 1], qb1_);                                 \
        qa2_ = fma2(va1_.x, e2[2*g_ + 2], qa2_);                                 \
        qb2_ = fma2(vb1_.x, e2[2*g_ + 2], qb2_);                                 \
        qa3_ = fma2(va1_.y, e2[2*g_ + 3], qa3_);                                 \
        qb3_ = fma2(vb1_.y, e2[2*g_ + 3], qb3_);                                 \
    }                                                                            \
    ull qA_ = add2(add2(qa0_, qa1_), add2(qa2_, qa3_));                          \
    ull qB_ = add2(add2(qb0_, qb1_), add2(qb2_, qb3_));                          \
    float qx_, qy_;                                                              \
    unpack2(qA_, qx_, qy_);                                                      \
    if (M0) { px0 = qx_ * ex0_; py0 = qy_ * ey0_; }                              \
    unpack2(qB_, qx_, qy_);                                                      \
    if (M1) { px1 = qx_ * ex1_; py1 = qy_ * ey1_; }                              \
    if (REN) {                                                                   \
        /* p strictly positive & normal -> int-bit max valid */                  \
        int mb0_ = __reduce_max_sync(FULLMASK, __float_as_int(fmaxf(px0, py0))); \
        int mb1_ = __reduce_max_sync(FULLMASK, __float_as_int(fmaxf(px1, py1))); \
        int e0_ = mb0_ >> 23, e1_ = mb1_ >> 23;                                  \
        float i0_ = __int_as_float((254 - e0_) << 23);  /* 2^(127-e), exact */   \
        float i1_ = __int_as_float((254 - e1_) << 23);                           \
        px0 *= i0_; py0 *= i0_; logZ0 += (float)(e0_ - 127) * LN2F;              \
        px1 *= i1_; py1 *= i1_; logZ1 += (float)(e1_ - 127) * LN2F;              \
    }                                                                            \
    ((float4*)(POUT0))[lane] = make_float4(px0, px0, py0, py0);                  \
    ((float4*)(POUT1))[lane] = make_float4(px1, px1, py1, py1);                  \
    __syncwarp();                                                                \
} while (0)

__global__ void __launch_bounds__(THREADS, 1) crf_forward(
    const float* __restrict__ emissions,   // [B, T, C]
    const int*   __restrict__ tags,        // [B, T]
    const int*   __restrict__ mask,        // [B, T]
    const float* __restrict__ trans,       // [C, C]
    const float* __restrict__ startt,      // [C]
    const float* __restrict__ endt,        // [C]
    float*       __restrict__ out)         // [1]
{
    // p buffers: [warp][pingpong][batch][NC], duplicated pairs so a broadcast
    // LDS.128 yields two (p,p) pairs feeding fma.rn.f32x2 directly.
    __shared__ __align__(16) ull pbuf[WPB][2][2][NC];
    __shared__ bool s_last;

    const int wid  = threadIdx.x >> 5;
    const int lane = threadIdx.x & 31;
    const int w    = blockIdx.x * WPB + wid;   // 0..255
    const int b0   = 2 * w, b1 = 2 * w + 1;
    const int j0   = lane * 2;

    ull* P00 = pbuf[wid][0][0];  ull* P01 = pbuf[wid][0][1];
    ull* P10 = pbuf[wid][1][0];  ull* P11 = pbuf[wid][1][1];

    const float* em0p = emissions + (size_t)b0 * NT * NC;
    const float* em1p = emissions + (size_t)b1 * NT * NC;
    const int*   mk0  = mask + (size_t)b0 * NT;
    const int*   mk1  = mask + (size_t)b1 * NT;

    // ---- startup long-latency loads first (both batches) ----
    float2 a_em0 = *(const float2*)(em0p + j0);
    float2 b_em0 = *(const float2*)(em1p + j0);
    float2 aP0 = *(const float2*)(em0p + (size_t)1 * NC + j0);
    float2 aP1 = *(const float2*)(em0p + (size_t)2 * NC + j0);
    float2 aP2 = *(const float2*)(em0p + (size_t)3 * NC + j0);
    float2 bP0 = *(const float2*)(em1p + (size_t)1 * NC + j0);
    float2 bP1 = *(const float2*)(em1p + (size_t)2 * NC + j0);
    float2 bP2 = *(const float2*)(em1p + (size_t)3 * NC + j0);
    int4 amk03 = *(const int4*)(mk0);
    int4 bmk03 = *(const int4*)(mk1);
    int4 amc   = *(const int4*)(mk0 + 4);
    int4 bmc   = *(const int4*)(mk1 + 4);
    float2 ac0 = *(const float2*)(em0p + (size_t)4 * NC + j0);
    float2 ac1 = *(const float2*)(em0p + (size_t)5 * NC + j0);
    float2 ac2 = *(const float2*)(em0p + (size_t)6 * NC + j0);
    float2 ac3 = *(const float2*)(em0p + (size_t)7 * NC + j0);
    float2 bc0 = *(const float2*)(em1p + (size_t)4 * NC + j0);
    float2 bc1 = *(const float2*)(em1p + (size_t)5 * NC + j0);
    float2 bc2 = *(const float2*)(em1p + (size_t)6 * NC + j0);
    float2 bc3 = *(const float2*)(em1p + (size_t)7 * NC + j0);
    float2 st2 = *(const float2*)(startt + j0);
    float2 et2 = *(const float2*)(endt + j0);

    // ---- E = exp(transitions), lane's two columns, shared by both chains ----
    ull e2[NC];
#pragma unroll
    for (int i = 0; i < NC; i++) {
        float2 tv = *(const float2*)(trans + i * NC + j0);
        e2[i] = pack2(__expf(tv.x), __expf(tv.y));
    }

    // ---- joint scores (log numerators) for both batches ----
    float num0 = 0.f, num1 = 0.f;
    {
        const int* tg0 = tags + (size_t)b0 * NT;
        const int* tg1 = tags + (size_t)b1 * NT;
        int cnt0 = 0, cnt1 = 0;
#pragma unroll 2
        for (int t = lane; t < NT; t += 32) {
            int t0a = tg0[t], m0a = mk0[t];
            int t1a = tg1[t], m1a = mk1[t];
            cnt0 += m0a; cnt1 += m1a;
            if (t > 0 && m0a)
                num0 += trans[tg0[t - 1] * NC + t0a] + em0p[(size_t)t * NC + t0a];
            if (t > 0 && m1a)
                num1 += trans[tg1[t - 1] * NC + t1a] + em1p[(size_t)t * NC + t1a];
        }
        cnt0 = __reduce_add_sync(FULLMASK, cnt0);
        cnt1 = __reduce_add_sync(FULLMASK, cnt1);
#pragma unroll
        for (int o = 16; o > 0; o >>= 1) {
            num0 += __shfl_down_sync(FULLMASK, num0, o);
            num1 += __shfl_down_sync(FULLMASK, num1, o);
        }
        if (lane == 0) {
            int ta = tg0[0], tb = tg1[0];
            num0 += startt[ta] + em0p[ta] + endt[tg0[cnt0 - 1]];
            num1 += startt[tb] + em1p[tb] + endt[tg1[cnt1 - 1]];
        }
    }

    // ---- init t = 0 (values may be negative -> shfl fmax trees) ----
    float ax0 = st2.x + a_em0.x, ay0 = st2.y + a_em0.y;
    float ax1 = st2.x + b_em0.x, ay1 = st2.y + b_em0.y;
    float m0r = fmaxf(ax0, ay0), m1r = fmaxf(ax1, ay1);
#pragma unroll
    for (int o = 16; o > 0; o >>= 1) {
        m0r = fmaxf(m0r, __shfl_xor_sync(FULLMASK, m0r, o));
        m1r = fmaxf(m1r, __shfl_xor_sync(FULLMASK, m1r, o));
    }
    float logZ0 = m0r, logZ1 = m1r;
    float px0 = __expf(ax0 - m0r), py0 = __expf(ay0 - m0r);
    float px1 = __expf(ax1 - m1r), py1 = __expf(ay1 - m1r);
    ((float4*)P00)[lane] = make_float4(px0, px0, py0, py0);
    ((float4*)P01)[lane] = make_float4(px1, px1, py1, py1);
    __syncwarp();

    // ---- prologue t = 1..3 (buffers: 0->1, 1->0, 0->1; renorm on last) ----
    STEP2(P00, P10, P01, P11, aP0, amk03.y, bP0, bmk03.y, false);
    STEP2(P10, P00, P11, P01, aP1, amk03.z, bP1, bmk03.z, false);
    STEP2(P00, P10, P01, P11, aP2, amk03.w, bP2, bmk03.w, true);

    // ---- main loop: groups of 4 (buffers 1->0->1->0->1), prefetch 4 ahead ----
#pragma unroll 1
    for (int t0 = 4; t0 < NT; t0 += 4) {
        float2 an0 = ac0, an1 = ac1, an2 = ac2, an3 = ac3;
        float2 bn0 = bc0, bn1 = bc1, bn2 = bc2, bn3 = bc3;
        int4   amn = amc, bmn = bmc;
        if (t0 + 4 < NT) {
            const float* pa4 = em0p + (size_t)(t0 + 4) * NC + j0;
            const float* pb4 = em1p + (size_t)(t0 + 4) * NC + j0;
            an0 = *(const float2*)(pa4);
            bn0 = *(const float2*)(pb4);
            an1 = *(const float2*)(pa4 + NC);
            bn1 = *(const float2*)(pb4 + NC);
            an2 = *(const float2*)(pa4 + 2 * NC);
            bn2 = *(const float2*)(pb4 + 2 * NC);
            an3 = *(const float2*)(pa4 + 3 * NC);
            bn3 = *(const float2*)(pb4 + 3 * NC);
            amn = *(const int4*)(mk0 + t0 + 4);
            bmn = *(const int4*)(mk1 + t0 + 4);
        }
        STEP2(P10, P00, P11, P01, ac0, amc.x, bc0, bmc.x, false);
        STEP2(P00, P10, P01, P11, ac1, amc.y, bc1, bmc.y, false);
        STEP2(P10, P00, P11, P01, ac2, amc.z, bc2, bmc.z, false);
        STEP2(P00, P10, P01, P11, ac3, amc.w, bc3, bmc.w, true);
        ac0 = an0; ac1 = an1; ac2 = an2; ac3 = an3; amc = amn;
        bc0 = bn0; bc1 = bn1; bc2 = bn2; bc3 = bn3; bmc = bmn;
    }

    // ---- log denominators & per-batch losses (final p is in registers) ----
    float eex = __expf(et2.x), eey = __expf(et2.y);
    float c0 = px0 * eex + py0 * eey;
    float c1 = px1 * eex + py1 * eey;
#pragma unroll
    for (int o = 16; o > 0; o >>= 1) {
        c0 += __shfl_down_sync(FULLMASK, c0, o);
        c1 += __shfl_down_sync(FULLMASK, c1, o);
    }
    if (lane == 0) {
        g_partial[b0] = logZ0 + __logf(c0) - num0;
        g_partial[b1] = logZ1 + __logf(c1) - num1;
    }

    // ---- fused final reduction: last CTA to finish reduces all 512 ----
    __syncthreads();
    if (threadIdx.x == 0) {
        __threadfence();
        unsigned prev = atomicAdd(&g_done, 1u);
        s_last = (prev == gridDim.x - 1);
    }
    __syncthreads();
    if (s_last && wid == 0) {
        __threadfence();
        float s = 0.f;
        const float4* gp = (const float4*)g_partial;
#pragma unroll
        for (int k = 0; k < 4; k++) {
            float4 v = __ldcg(gp + lane + 32 * k);
            s += (v.x + v.y) + (v.z + v.w);
        }
#pragma unroll
        for (int o = 16; o > 0; o >>= 1)
            s += __shfl_down_sync(FULLMASK, s, o);
        if (lane == 0) {
            out[0] = s * (1.0f / (float)NB);
            g_done = 0;   // reset for next graph replay (deterministic)
        }
    }
}

extern "C" void kernel_launch(void* const* d_in, const int* in_sizes, int n_in,
                              void* d_out, int out_size) {
    const float* emissions = (const float*)d_in[0];
    const int*   tags      = (const int*)d_in[1];
    const int*   mask      = (const int*)d_in[2];
    const float* trans     = (const float*)d_in[3];
    const float* startt    = (const float*)d_in[4];
    const float* endt      = (const float*)d_in[5];
    (void)in_sizes; (void)n_in; (void)out_size;

    crf_forward<<<NB / (2 * WPB), THREADS>>>(emissions, tags, mask, trans,
                                             startt, endt, (float*)d_out);
}

// round 10
// speedup vs baseline: 2.8395x; 2.8395x over previous
#include <cuda_runtime.h>
#include <cstdint>

typedef unsigned long long ull;

#define NB 512
#define NT 512
#define NC 64
#define HALF_T 256        // fw owns t in [0,256); bw owns [256,512)
#define PAIRS 4           // batches per CTA
#define THREADS 256       // 8 warps = 4 (fw,bw) pairs
#define FULLMASK 0xffffffffu
#define LN2F 0.6931471805599453f

__device__ float    g_partial[NB];
__device__ unsigned g_done;

static __device__ __forceinline__ ull fma2(ull a, ull b, ull c) {
    ull d; asm("fma.rn.f32x2 %0,%1,%2,%3;" : "=l"(d) : "l"(a), "l"(b), "l"(c)); return d;
}
static __device__ __forceinline__ ull add2(ull a, ull b) {
    ull d; asm("add.rn.f32x2 %0,%1,%2;" : "=l"(d) : "l"(a), "l"(b)); return d;
}
static __device__ __forceinline__ ull pack2(float x, float y) {
    ull d; asm("mov.b64 %0,{%1,%2};" : "=l"(d) : "f"(x), "f"(y)); return d;
}
static __device__ __forceinline__ void unpack2(ull v, float& x, float& y) {
    asm("mov.b64 {%0,%1},%2;" : "=f"(x), "=f"(y) : "l"(v));
}

// 64-wide GEMV on this warp's buffer: QX/QY = dot of duplicated-pair vector
// with this lane's two e2 columns. (e2, lane in scope at expansion site.)
#define GEMV64(SRC, QX, QY) do {                                                 \
    const ulonglong2* pb_ = (const ulonglong2*)(SRC);                            \
    ull q0_=0, q1_=0, q2_=0, q3_=0;                                              \
    _Pragma("unroll")                                                            \
    for (int g_ = 0; g_ < 16; g_++) {                                            \
        ulonglong2 v_ = pb_[2 * g_];                                             \
        ulonglong2 w_ = pb_[2 * g_ + 1];                                         \
        q0_ = fma2(v_.x, e2[4 * g_ + 0], q0_);                                   \
        q1_ = fma2(v_.y, e2[4 * g_ + 1], q1_);                                   \
        q2_ = fma2(w_.x, e2[4 * g_ + 2], q2_);                                   \
        q3_ = fma2(w_.y, e2[4 * g_ + 3], q3_);                                   \
    }                                                                            \
    ull qq_ = add2(add2(q0_, q1_), add2(q2_, q3_));                              \
    unpack2(qq_, QX, QY);                                                        \
} while (0)

// Exact power-of-2 renorm of (px,py); p strictly positive -> int-bit max valid.
#define RENORM2() do {                                                           \
    int mb_ = __reduce_max_sync(FULLMASK, __float_as_int(fmaxf(px, py)));        \
    int e_  = mb_ >> 23;                                                         \
    float inv_ = __int_as_float((254 - e_) << 23);   /* 2^(127-e), exact */      \
    px *= inv_; py *= inv_;                                                      \
    logZ += (float)(e_ - 127) * LN2F;                                            \
} while (0)

// Forward step: q = E^T p; masked: p = q * exp(emit_t); store duplicated pairs.
#define STEP_F(EM, M, REN) do {                                                  \
    float ex_ = __expf((EM).x), ey_ = __expf((EM).y);                            \
    float qx_, qy_; GEMV64(pbuf[wid][cur], qx_, qy_);                            \
    if (M) { px = qx_ * ex_; py = qy_ * ey_; }                                   \
    if (REN) RENORM2();                                                          \
    cur ^= 1;                                                                    \
    ((float4*)pbuf[wid][cur])[lane] = make_float4(px, px, py, py);               \
    __syncwarp();                                                                \
} while (0)

// Backward step: c = E v; masked: beta = c; store v' = beta * exp(emit_{u-1}).
#define STEP_B(EM, M, REN) do {                                                  \
    float ex_ = __expf((EM).x), ey_ = __expf((EM).y);                            \
    float qx_, qy_; GEMV64(pbuf[wid][cur], qx_, qy_);                            \
    if (M) { px = qx_; py = qy_; }                                               \
    if (REN) RENORM2();                                                          \
    float wx_ = px * ex_, wy_ = py * ey_;                                        \
    cur ^= 1;                                                                    \
    ((float4*)pbuf[wid][cur])[lane] = make_float4(wx_, wx_, wy_, wy_);           \
    __syncwarp();                                                                \
} while (0)

__global__ void __launch_bounds__(THREADS, 1) crf_forward(
    const float* __restrict__ emissions,   // [B, T, C]
    const int*   __restrict__ tags,        // [B, T]
    const int*   __restrict__ mask,        // [B, T]
    const float* __restrict__ trans,       // [C, C]
    const float* __restrict__ startt,      // [C]
    const float* __restrict__ endt,        // [C]
    float*       __restrict__ out)         // [1]
{
    // Per-warp double-buffered state vector, duplicated pairs: entry i holds
    // (v[i], v[i]) so a broadcast LDS.128 feeds fma.rn.f32x2 directly.
    __shared__ __align__(16) ull    pbuf[8][2][NC];
    __shared__ __align__(8)  float2 bbuf[PAIRS][32];   // beta_255 (plain)
    __shared__ float s_logZb[PAIRS];
    __shared__ float s_numb[PAIRS];
    __shared__ bool  s_last;

    const int wid  = threadIdx.x >> 5;
    const int lane = threadIdx.x & 31;
    const int pair = wid >> 1;
    const int role = wid & 1;                 // 0 = forward, 1 = backward
    const int b    = blockIdx.x * PAIRS + pair;
    const int j0   = lane * 2;

    const float* em = emissions + (size_t)b * NT * NC;
    const int*   tg = tags + (size_t)b * NT;
    const int*   mk = mask + (size_t)b * NT;

    float2 et2 = *(const float2*)(endt + j0);

    ull e2[NC];
    int cur = 0;
    float px, py, logZ;

    if (role == 0) {
        // ========================= FORWARD (t = 0..255) =========================
        float2 em0  = *(const float2*)(em + j0);
        float2 emP0 = *(const float2*)(em + (size_t)1 * NC + j0);
        float2 emP1 = *(const float2*)(em + (size_t)2 * NC + j0);
        float2 emP2 = *(const float2*)(em + (size_t)3 * NC + j0);
        int4   mk03 = *(const int4*)(mk);
        int4   mc   = *(const int4*)(mk + 4);
        float2 emc0 = *(const float2*)(em + (size_t)4 * NC + j0);
        float2 emc1 = *(const float2*)(em + (size_t)5 * NC + j0);
        float2 emc2 = *(const float2*)(em + (size_t)6 * NC + j0);
        float2 emc3 = *(const float2*)(em + (size_t)7 * NC + j0);
        float2 st2  = *(const float2*)(startt + j0);

        // e2 = exp(transitions) columns j0, j0+1
#pragma unroll
        for (int i = 0; i < NC; i++) {
            float2 tv = *(const float2*)(trans + i * NC + j0);
            e2[i] = pack2(__expf(tv.x), __expf(tv.y));
        }

        // numerator, first half: start term + t in [1, 256)
        float num = 0.f;
#pragma unroll 2
        for (int t = lane; t < HALF_T; t += 32) {
            int tt = tg[t];
            if (t > 0 && mk[t])
                num += trans[tg[t - 1] * NC + tt] + em[(size_t)t * NC + tt];
        }
#pragma unroll
        for (int o = 16; o > 0; o >>= 1)
            num += __shfl_down_sync(FULLMASK, num, o);
        if (lane == 0) {
            int t0 = tg[0];
            num += startt[t0] + em[t0];
        }

        // init t = 0 (values may be negative -> shfl fmax tree)
        float ax = st2.x + em0.x, ay = st2.y + em0.y;
        float m0 = fmaxf(ax, ay);
#pragma unroll
        for (int o = 16; o > 0; o >>= 1)
            m0 = fmaxf(m0, __shfl_xor_sync(FULLMASK, m0, o));
        logZ = m0;
        px = __expf(ax - m0);
        py = __expf(ay - m0);
        ((float4*)pbuf[wid][0])[lane] = make_float4(px, px, py, py);
        __syncwarp();

        STEP_F(emP0, mk03.y, false);
        STEP_F(emP1, mk03.z, false);
        STEP_F(emP2, mk03.w, true);

#pragma unroll 1
        for (int t0 = 4; t0 < HALF_T; t0 += 4) {
            float2 en0 = emc0, en1 = emc1, en2 = emc2, en3 = emc3;
            int4   mn  = mc;
            if (t0 + 4 < HALF_T) {
                const float* p4 = em + (size_t)(t0 + 4) * NC + j0;
                en0 = *(const float2*)(p4);
                en1 = *(const float2*)(p4 + NC);
                en2 = *(const float2*)(p4 + 2 * NC);
                en3 = *(const float2*)(p4 + 3 * NC);
                mn  = *(const int4*)(mk + t0 + 4);
            }
            STEP_F(emc0, mc.x, false);
            STEP_F(emc1, mc.y, false);
            STEP_F(emc2, mc.z, false);
            STEP_F(emc3, mc.w, true);
            emc0 = en0; emc1 = en1; emc2 = en2; emc3 = en3; mc = mn;
        }

        __syncthreads();   // beta_255, logZb, num_b published by bw warp

        float2 bb = bbuf[pair][lane];
        float contrib = px * bb.x + py * bb.y;
#pragma unroll
        for (int o = 16; o > 0; o >>= 1)
            contrib += __shfl_down_sync(FULLMASK, contrib, o);
        if (lane == 0)
            g_partial[b] = logZ + s_logZb[pair] + __logf(contrib)
                           - (num + s_numb[pair]);
    } else {
        // ========================= BACKWARD (t = 511..256) ======================
        // beta_u: step u consumes mask[u] and (for the store) emit[u-1].
        float2 emI  = *(const float2*)(em + (size_t)511 * NC + j0);  // e_511
        float2 eP0  = *(const float2*)(em + (size_t)510 * NC + j0);
        float2 eP1  = *(const float2*)(em + (size_t)509 * NC + j0);
        float2 eP2  = *(const float2*)(em + (size_t)508 * NC + j0);
        int mk511 = mk[511], mk510 = mk[510], mk509 = mk[509];
        // first main group (u0 = 508): emissions 507..504, masks 508..505
        float2 be0 = *(const float2*)(em + (size_t)507 * NC + j0);
        float2 be1 = *(const float2*)(em + (size_t)506 * NC + j0);
        float2 be2 = *(const float2*)(em + (size_t)505 * NC + j0);
        float2 be3 = *(const float2*)(em + (size_t)504 * NC + j0);
        int m0g = mk[508], m1g = mk[507], m2g = mk[506], m3g = mk[505];
        int mk256 = mk[256];

        // e2 = exp(transitions) ROWS j0, j0+1 (E, not E^T)
#pragma unroll
        for (int k = 0; k < NC; k++) {
            float tv0 = trans[j0 * NC + k];
            float tv1 = trans[(j0 + 1) * NC + k];
            e2[k] = pack2(__expf(tv0), __expf(tv1));
        }

        // numerator, second half: t in [256, 512) + end term (needs full cnt)
        float num = 0.f;
        int   cnt = 0;
#pragma unroll 2
        for (int t = lane; t < NT; t += 32) {
            int m = mk[t];
            cnt += m;
            if (t >= HALF_T && m) {
                int tt = tg[t];
                num += trans[tg[t - 1] * NC + tt] + em[(size_t)t * NC + tt];
            }
        }
        cnt = __reduce_add_sync(FULLMASK, cnt);
#pragma unroll
        for (int o = 16; o > 0; o >>= 1)
            num += __shfl_down_sync(FULLMASK, num, o);
        if (lane == 0)
            s_numb[pair] = num + endt[tg[cnt - 1]];

        // init: beta_511 = exp(end); store v_511 = e_511 * beta_511
        px = __expf(et2.x);
        py = __expf(et2.y);
        logZ = 0.f;
        {
            float wx = px * __expf(emI.x), wy = py * __expf(emI.y);
            ((float4*)pbuf[wid][0])[lane] = make_float4(wx, wx, wy, wy);
        }
        __syncwarp();

        STEP_B(eP0, mk511, false);
        STEP_B(eP1, mk510, false);
        STEP_B(eP2, mk509, true);

#pragma unroll 1
        for (int u0 = 508; u0 >= 260; u0 -= 4) {
            float2 bn0 = be0, bn1 = be1, bn2 = be2, bn3 = be3;
            int n0 = m0g, n1 = m1g, n2 = m2g, n3 = m3g;
            if (u0 > 260) {
                const int u1 = u0 - 4;
                const float* p4 = em + (size_t)(u1 - 4) * NC + j0;
                bn0 = *(const float2*)(p4 + 3 * NC);   // e_{u1-1}
                bn1 = *(const float2*)(p4 + 2 * NC);   // e_{u1-2}
                bn2 = *(const float2*)(p4 + NC);       // e_{u1-3}
                bn3 = *(const float2*)(p4);            // e_{u1-4}
                n0 = mk[u1]; n1 = mk[u1 - 1]; n2 = mk[u1 - 2]; n3 = mk[u1 - 3];
            }
            STEP_B(be0, m0g, false);
            STEP_B(be1, m1g, false);
            STEP_B(be2, m2g, false);
            STEP_B(be3, m3g, true);
            be0 = bn0; be1 = bn1; be2 = bn2; be3 = bn3;
            m0g = n0; m1g = n1; m2g = n2; m3g = n3;
        }

        // final step u = 256: select only (no emission, no store)
        {
            float qx_, qy_;
            GEMV64(pbuf[wid][cur], qx_, qy_);
            if (mk256) { px = qx_; py = qy_; }
        }
        bbuf[pair][lane] = make_float2(px, py);
        if (lane == 0) s_logZb[pair] = logZ;

        __syncthreads();   // matches fw warp's barrier
    }

    // ---- fused final reduction: last CTA to finish reduces all 512 ----
    __syncthreads();
    if (threadIdx.x == 0) {
        __threadfence();
        unsigned prev = atomicAdd(&g_done, 1u);
        s_last = (prev == gridDim.x - 1);
    }
    __syncthreads();
    if (s_last && wid == 0) {
        __threadfence();
        float s = 0.f;
        const float4* gp = (const float4*)g_partial;
#pragma unroll
        for (int k = 0; k < 4; k++) {
            float4 v = __ldcg(gp + lane + 32 * k);
            s += (v.x + v.y) + (v.z + v.w);
        }
#pragma unroll
        for (int o = 16; o > 0; o >>= 1)
            s += __shfl_down_sync(FULLMASK, s, o);
        if (lane == 0) {
            out[0] = s * (1.0f / (float)NB);
            g_done = 0;   // reset for next graph replay (deterministic)
        }
    }
}

extern "C" void kernel_launch(void* const* d_in, const int* in_sizes, int n_in,
                              void* d_out, int out_size) {
    const float* emissions = (const float*)d_in[0];
    const int*   tags      = (const int*)d_in[1];
    const int*   mask      = (const int*)d_in[2];
    const float* trans     = (const float*)d_in[3];
    const float* startt    = (const float*)d_in[4];
    const float* endt      = (const float*)d_in[5];
    (void)in_sizes; (void)n_in; (void)out_size;

    crf_forward<<<NB / PAIRS, THREADS>>>(emissions, tags, mask, trans, startt,
                                         endt, (float*)d_out);
}

// round 11
// speedup vs baseline: 3.5540x; 1.2516x over previous
#include <cuda_runtime.h>
#include <cuda_bf16.h>
#include <cstdint>

typedef unsigned long long ull;

#define NB 512
#define NT 512
#define NC 64
#define HALF_T 256        // fw owns t in [0,256); bw owns [256,512)
#define PAIRS 4           // batches per CTA
#define THREADS 256       // 8 warps = 4 (fw,bw) pairs
#define FULLMASK 0xffffffffu
#define LN2F 0.6931471805599453f

__device__ float    g_partial[NB];
__device__ unsigned g_done;

static __device__ __forceinline__ __nv_bfloat162 u2b(unsigned u) {
    __nv_bfloat162 r; *reinterpret_cast<unsigned*>(&r) = u; return r;
}
static __device__ __forceinline__ unsigned b2u(__nv_bfloat162 b) {
    return *reinterpret_cast<unsigned*>(&b);
}

// 64-wide GEMV in bf16: buffer holds duplicated bf16x2 pairs (p_i, p_i);
// e2[i] = (E[i][c0], E[i][c1]) bf16x2. 16x LDS.128 + 64x HFMA2.
// Final accumulator combine in f32 for accuracy.
#define GEMV64H(SRC, QX, QY) do {                                                \
    const uint4* pb_ = (const uint4*)(SRC);                                      \
    __nv_bfloat162 a0_ = u2b(0u), a1_ = u2b(0u), a2_ = u2b(0u), a3_ = u2b(0u);   \
    _Pragma("unroll")                                                            \
    for (int g_ = 0; g_ < 16; g_++) {                                            \
        uint4 v_ = pb_[g_];                                                      \
        a0_ = __hfma2(u2b(v_.x), e2[4 * g_ + 0], a0_);                           \
        a1_ = __hfma2(u2b(v_.y), e2[4 * g_ + 1], a1_);                           \
        a2_ = __hfma2(u2b(v_.z), e2[4 * g_ + 2], a2_);                           \
        a3_ = __hfma2(u2b(v_.w), e2[4 * g_ + 3], a3_);                           \
    }                                                                            \
    float2 f0_ = __bfloat1622float2(a0_);                                        \
    float2 f1_ = __bfloat1622float2(a1_);                                        \
    float2 f2_ = __bfloat1622float2(a2_);                                        \
    float2 f3_ = __bfloat1622float2(a3_);                                        \
    QX = (f0_.x + f1_.x) + (f2_.x + f3_.x);                                      \
    QY = (f0_.y + f1_.y) + (f2_.y + f3_.y);                                      \
} while (0)

// Exact power-of-2 renorm of f32 (px,py); p strictly positive.
#define RENORM2() do {                                                           \
    int mb_ = __reduce_max_sync(FULLMASK, __float_as_int(fmaxf(px, py)));        \
    int e_  = mb_ >> 23;                                                         \
    float inv_ = __int_as_float((254 - e_) << 23);   /* 2^(127-e), exact */      \
    px *= inv_; py *= inv_;                                                      \
    logZ += (float)(e_ - 127) * LN2F;                                            \
} while (0)

// Store f32 pair as two duplicated bf16x2 entries (one STS.64 per lane).
#define STORE_DUP(OUT, VX, VY) do {                                              \
    unsigned lo_ = b2u(__float2bfloat162_rn(VX));                                \
    unsigned hi_ = b2u(__float2bfloat162_rn(VY));                                \
    ((ull*)(OUT))[lane] = (ull)lo_ | ((ull)hi_ << 32);                           \
} while (0)

// Forward step: q = E^T p; masked: p = q * exp(emit_t).
#define STEP_F(EM, M, REN) do {                                                  \
    float ex_ = __expf((EM).x), ey_ = __expf((EM).y);                            \
    float qx_, qy_; GEMV64H(pbuf[wid][cur], qx_, qy_);                           \
    if (M) { px = qx_ * ex_; py = qy_ * ey_; }                                   \
    if (REN) RENORM2();                                                          \
    cur ^= 1;                                                                    \
    STORE_DUP(pbuf[wid][cur], px, py);                                           \
    __syncwarp();                                                                \
} while (0)

// Backward step: c = E v; masked: beta = c; store v' = beta * exp(emit_{u-1}).
#define STEP_B(EM, M, REN) do {                                                  \
    float ex_ = __expf((EM).x), ey_ = __expf((EM).y);                            \
    float qx_, qy_; GEMV64H(pbuf[wid][cur], qx_, qy_);                           \
    if (M) { px = qx_; py = qy_; }                                               \
    if (REN) RENORM2();                                                          \
    float wx_ = px * ex_, wy_ = py * ey_;                                        \
    cur ^= 1;                                                                    \
    STORE_DUP(pbuf[wid][cur], wx_, wy_);                                         \
    __syncwarp();                                                                \
} while (0)

__global__ void __launch_bounds__(THREADS, 1) crf_forward(
    const float* __restrict__ emissions,   // [B, T, C]
    const int*   __restrict__ tags,        // [B, T]
    const int*   __restrict__ mask,        // [B, T]
    const float* __restrict__ trans,       // [C, C]
    const float* __restrict__ startt,      // [C]
    const float* __restrict__ endt,        // [C]
    float*       __restrict__ out)         // [1]
{
    // Per-warp double-buffered bf16 state: entry i = bf16x2(v[i], v[i]).
    __shared__ __align__(16) unsigned pbuf[8][2][NC];
    __shared__ __align__(8)  float2   bbuf[PAIRS][32];   // beta_255 (f32)
    __shared__ float s_logZb[PAIRS];
    __shared__ float s_numb[PAIRS];
    __shared__ bool  s_last;

    const int wid  = threadIdx.x >> 5;
    const int lane = threadIdx.x & 31;
    const int pair = wid >> 1;
    const int role = wid & 1;                 // 0 = forward, 1 = backward
    const int b    = blockIdx.x * PAIRS + pair;
    const int j0   = lane * 2;

    const float* em = emissions + (size_t)b * NT * NC;
    const int*   tg = tags + (size_t)b * NT;
    const int*   mk = mask + (size_t)b * NT;

    float2 et2 = *(const float2*)(endt + j0);

    __nv_bfloat162 e2[NC];
    int cur = 0;
    float px, py, logZ;

    if (role == 0) {
        // ========================= FORWARD (t = 0..255) =========================
        float2 em0  = *(const float2*)(em + j0);
        float2 emP0 = *(const float2*)(em + (size_t)1 * NC + j0);
        float2 emP1 = *(const float2*)(em + (size_t)2 * NC + j0);
        float2 emP2 = *(const float2*)(em + (size_t)3 * NC + j0);
        int4   mk03 = *(const int4*)(mk);
        int4   mc   = *(const int4*)(mk + 4);
        float2 emc0 = *(const float2*)(em + (size_t)4 * NC + j0);
        float2 emc1 = *(const float2*)(em + (size_t)5 * NC + j0);
        float2 emc2 = *(const float2*)(em + (size_t)6 * NC + j0);
        float2 emc3 = *(const float2*)(em + (size_t)7 * NC + j0);
        float2 st2  = *(const float2*)(startt + j0);

        // e2 = exp(transitions) columns j0, j0+1 (bf16x2)
#pragma unroll
        for (int i = 0; i < NC; i++) {
            float2 tv = *(const float2*)(trans + i * NC + j0);
            e2[i] = __floats2bfloat162_rn(__expf(tv.x), __expf(tv.y));
        }

        // numerator (f32), first half: start term + t in [1, 256)
        float num = 0.f;
#pragma unroll 2
        for (int t = lane; t < HALF_T; t += 32) {
            int tt = tg[t];
            if (t > 0 && mk[t])
                num += trans[tg[t - 1] * NC + tt] + em[(size_t)t * NC + tt];
        }
#pragma unroll
        for (int o = 16; o > 0; o >>= 1)
            num += __shfl_down_sync(FULLMASK, num, o);
        if (lane == 0) {
            int t0 = tg[0];
            num += startt[t0] + em[t0];
        }

        // init t = 0 (values may be negative -> shfl fmax tree)
        float ax = st2.x + em0.x, ay = st2.y + em0.y;
        float m0 = fmaxf(ax, ay);
#pragma unroll
        for (int o = 16; o > 0; o >>= 1)
            m0 = fmaxf(m0, __shfl_xor_sync(FULLMASK, m0, o));
        logZ = m0;
        px = __expf(ax - m0);
        py = __expf(ay - m0);
        STORE_DUP(pbuf[wid][0], px, py);
        __syncwarp();

        STEP_F(emP0, mk03.y, false);
        STEP_F(emP1, mk03.z, false);
        STEP_F(emP2, mk03.w, true);

#pragma unroll 1
        for (int t0 = 4; t0 < HALF_T; t0 += 4) {
            float2 en0 = emc0, en1 = emc1, en2 = emc2, en3 = emc3;
            int4   mn  = mc;
            if (t0 + 4 < HALF_T) {
                const float* p4 = em + (size_t)(t0 + 4) * NC + j0;
                en0 = *(const float2*)(p4);
                en1 = *(const float2*)(p4 + NC);
                en2 = *(const float2*)(p4 + 2 * NC);
                en3 = *(const float2*)(p4 + 3 * NC);
                mn  = *(const int4*)(mk + t0 + 4);
            }
            STEP_F(emc0, mc.x, false);
            STEP_F(emc1, mc.y, false);
            STEP_F(emc2, mc.z, false);
            STEP_F(emc3, mc.w, true);
            emc0 = en0; emc1 = en1; emc2 = en2; emc3 = en3; mc = mn;
        }

        __syncthreads();   // beta_255, logZb, num_b published by bw warp

        float2 bb = bbuf[pair][lane];
        float contrib = px * bb.x + py * bb.y;
#pragma unroll
        for (int o = 16; o > 0; o >>= 1)
            contrib += __shfl_down_sync(FULLMASK, contrib, o);
        if (lane == 0)
            g_partial[b] = logZ + s_logZb[pair] + __logf(contrib)
                           - (num + s_numb[pair]);
    } else {
        // ========================= BACKWARD (t = 511..256) ======================
        float2 emI  = *(const float2*)(em + (size_t)511 * NC + j0);  // e_511
        float2 eP0  = *(const float2*)(em + (size_t)510 * NC + j0);
        float2 eP1  = *(const float2*)(em + (size_t)509 * NC + j0);
        float2 eP2  = *(const float2*)(em + (size_t)508 * NC + j0);
        int mk511 = mk[511], mk510 = mk[510], mk509 = mk[509];
        float2 be0 = *(const float2*)(em + (size_t)507 * NC + j0);
        float2 be1 = *(const float2*)(em + (size_t)506 * NC + j0);
        float2 be2 = *(const float2*)(em + (size_t)505 * NC + j0);
        float2 be3 = *(const float2*)(em + (size_t)504 * NC + j0);
        int m0g = mk[508], m1g = mk[507], m2g = mk[506], m3g = mk[505];
        int mk256 = mk[256];

        // e2 = exp(transitions) ROWS j0, j0+1 (E, not E^T) (bf16x2)
#pragma unroll
        for (int k = 0; k < NC; k++) {
            float tv0 = trans[j0 * NC + k];
            float tv1 = trans[(j0 + 1) * NC + k];
            e2[k] = __floats2bfloat162_rn(__expf(tv0), __expf(tv1));
        }

        // numerator (f32), second half + end term (needs full cnt)
        float num = 0.f;
        int   cnt = 0;
#pragma unroll 2
        for (int t = lane; t < NT; t += 32) {
            int m = mk[t];
            cnt += m;
            if (t >= HALF_T && m) {
                int tt = tg[t];
                num += trans[tg[t - 1] * NC + tt] + em[(size_t)t * NC + tt];
            }
        }
        cnt = __reduce_add_sync(FULLMASK, cnt);
#pragma unroll
        for (int o = 16; o > 0; o >>= 1)
            num += __shfl_down_sync(FULLMASK, num, o);
        if (lane == 0)
            s_numb[pair] = num + endt[tg[cnt - 1]];

        // init: beta_511 = exp(end); store v_511 = e_511 * beta_511
        px = __expf(et2.x);
        py = __expf(et2.y);
        logZ = 0.f;
        {
            float wx = px * __expf(emI.x), wy = py * __expf(emI.y);
            STORE_DUP(pbuf[wid][0], wx, wy);
        }
        __syncwarp();

        STEP_B(eP0, mk511, false);
        STEP_B(eP1, mk510, false);
        STEP_B(eP2, mk509, true);

#pragma unroll 1
        for (int u0 = 508; u0 >= 260; u0 -= 4) {
            float2 bn0 = be0, bn1 = be1, bn2 = be2, bn3 = be3;
            int n0 = m0g, n1 = m1g, n2 = m2g, n3 = m3g;
            if (u0 > 260) {
                const int u1 = u0 - 4;
                const float* p4 = em + (size_t)(u1 - 4) * NC + j0;
                bn0 = *(const float2*)(p4 + 3 * NC);   // e_{u1-1}
                bn1 = *(const float2*)(p4 + 2 * NC);   // e_{u1-2}
                bn2 = *(const float2*)(p4 + NC);       // e_{u1-3}
                bn3 = *(const float2*)(p4);            // e_{u1-4}
                n0 = mk[u1]; n1 = mk[u1 - 1]; n2 = mk[u1 - 2]; n3 = mk[u1 - 3];
            }
            STEP_B(be0, m0g, false);
            STEP_B(be1, m1g, false);
            STEP_B(be2, m2g, false);
            STEP_B(be3, m3g, true);
            be0 = bn0; be1 = bn1; be2 = bn2; be3 = bn3;
            m0g = n0; m1g = n1; m2g = n2; m3g = n3;
        }

        // final step u = 256: select only (no emission, no store)
        {
            float qx_, qy_;
            GEMV64H(pbuf[wid][cur], qx_, qy_);
            if (mk256) { px = qx_; py = qy_; }
        }
        bbuf[pair][lane] = make_float2(px, py);
        if (lane == 0) s_logZb[pair] = logZ;

        __syncthreads();   // matches fw warp's barrier
    }

    // ---- fused final reduction: last CTA to finish reduces all 512 ----
    __syncthreads();
    if (threadIdx.x == 0) {
        __threadfence();
        unsigned prev = atomicAdd(&g_done, 1u);
        s_last = (prev == gridDim.x - 1);
    }
    __syncthreads();
    if (s_last && wid == 0) {
        __threadfence();
        float s = 0.f;
        const float4* gp = (const float4*)g_partial;
#pragma unroll
        for (int k = 0; k < 4; k++) {
            float4 v = __ldcg(gp + lane + 32 * k);
            s += (v.x + v.y) + (v.z + v.w);
        }
#pragma unroll
        for (int o = 16; o > 0; o >>= 1)
            s += __shfl_down_sync(FULLMASK, s, o);
        if (lane == 0) {
            out[0] = s * (1.0f / (float)NB);
            g_done = 0;   // reset for next graph replay (deterministic)
        }
    }
}

extern "C" void kernel_launch(void* const* d_in, const int* in_sizes, int n_in,
                              void* d_out, int out_size) {
    const float* emissions = (const float*)d_in[0];
    const int*   tags      = (const int*)d_in[1];
    const int*   mask      = (const int*)d_in[2];
    const float* trans     = (const float*)d_in[3];
    const float* startt    = (const float*)d_in[4];
    const float* endt      = (const float*)d_in[5];
    (void)in_sizes; (void)n_in; (void)out_size;

    crf_forward<<<NB / PAIRS, THREADS>>>(emissions, tags, mask, trans, startt,
                                         endt, (float*)d_out);
}

// round 12
// speedup vs baseline: 3.7389x; 1.0520x over previous
#include <cuda_runtime.h>
#include <cuda_bf16.h>
#include <cstdint>

typedef unsigned long long ull;
typedef unsigned int u32;

#define NB 512
#define NT 512
#define NC 64
#define HALF_T 256        // fw owns t in [0,256); bw owns [256,512)
#define PAIRS 4           // batches per CTA
#define THREADS 256       // 8 warps = 4 (fw,bw) pairs
#define FULLMASK 0xffffffffu
#define LN2F 0.6931471805599453f

__device__ float    g_partial[NB];
__device__ unsigned g_done;

static __device__ __forceinline__ __nv_bfloat162 u2b(u32 u) {
    __nv_bfloat162 r; *reinterpret_cast<u32*>(&r) = u; return r;
}
static __device__ __forceinline__ u32 b2u(__nv_bfloat162 b) {
    return *reinterpret_cast<u32*>(&b);
}

// 64-wide GEMV in bf16: buffer holds duplicated bf16x2 pairs (p_i, p_i);
// e2[i] = (E[i][c0], E[i][c1]) bf16x2. 16x LDS.128 + 64x HFMA2, combined
// with 3 HADD2 -> packed (q_c0, q_c1). Entire hot path stays bf16.
#define GEMV64H(SRC, QOUT) do {                                                  \
    const uint4* pb_ = (const uint4*)(SRC);                                      \
    __nv_bfloat162 a0_ = u2b(0u), a1_ = u2b(0u), a2_ = u2b(0u), a3_ = u2b(0u);   \
    _Pragma("unroll")                                                            \
    for (int g_ = 0; g_ < 16; g_++) {                                            \
        uint4 v_ = pb_[g_];                                                      \
        a0_ = __hfma2(u2b(v_.x), e2[4 * g_ + 0], a0_);                           \
        a1_ = __hfma2(u2b(v_.y), e2[4 * g_ + 1], a1_);                           \
        a2_ = __hfma2(u2b(v_.z), e2[4 * g_ + 2], a2_);                           \
        a3_ = __hfma2(u2b(v_.w), e2[4 * g_ + 3], a3_);                           \
    }                                                                            \
    QOUT = __hadd2(__hadd2(a0_, a1_), __hadd2(a2_, a3_));                        \
} while (0)

// Exact power-of-2 renorm of packed-positive PP (bf16x2); 2^k exact in bf16.
#define RENORM_PP(PP) do {                                                       \
    float2 pf_ = __bfloat1622float2(PP);                                         \
    int mb_ = __reduce_max_sync(FULLMASK,                                        \
                                __float_as_int(fmaxf(pf_.x, pf_.y)));            \
    int e_  = mb_ >> 23;                         /* biased f32 exponent */       \
    u32 sb_ = (u32)(254 - e_) << 7;              /* bf16 bits of 2^(127-e) */    \
    PP = __hmul2(PP, u2b(sb_ | (sb_ << 16)));                                    \
    logZ += (float)(e_ - 127) * LN2F;                                            \
} while (0)

// Store packed (v0, v1) as two duplicated bf16x2 entries (one STS.64).
#define STORE_DUP(OUT, VV) do {                                                  \
    u32 r_  = b2u(VV);                                                           \
    u32 lo_ = __byte_perm(r_, r_, 0x1010);       /* (v0, v0) */                  \
    u32 hi_ = __byte_perm(r_, r_, 0x3232);       /* (v1, v1) */                  \
    ((ull*)(OUT))[lane] = (ull)lo_ | ((ull)hi_ << 32);                           \
} while (0)

// Forward step: q = E^T p; masked: p = q * exp(emit_t). All bf16.
#define STEP_F(EM, M, REN) do {                                                  \
    __nv_bfloat162 ee_ =                                                         \
        __floats2bfloat162_rn(__expf((EM).x), __expf((EM).y));                   \
    __nv_bfloat162 q_; GEMV64H(pbuf[wid][cur], q_);                              \
    if (M) pp = __hmul2(q_, ee_);                                                \
    if (REN) RENORM_PP(pp);                                                      \
    cur ^= 1;                                                                    \
    STORE_DUP(pbuf[wid][cur], pp);                                               \
    __syncwarp();                                                                \
} while (0)

// Backward step: c = E v; masked: beta = c; store v' = beta * exp(emit_{u-1}).
#define STEP_B(EM, M, REN) do {                                                  \
    __nv_bfloat162 ee_ =                                                         \
        __floats2bfloat162_rn(__expf((EM).x), __expf((EM).y));                   \
    __nv_bfloat162 q_; GEMV64H(pbuf[wid][cur], q_);                              \
    if (M) pp = q_;                                                              \
    if (REN) RENORM_PP(pp);                                                      \
    __nv_bfloat162 w_ = __hmul2(pp, ee_);                                        \
    cur ^= 1;                                                                    \
    STORE_DUP(pbuf[wid][cur], w_);                                               \
    __syncwarp();                                                                \
} while (0)

__global__ void __launch_bounds__(THREADS, 1) crf_forward(
    const float* __restrict__ emissions,   // [B, T, C]
    const int*   __restrict__ tags,        // [B, T]
    const int*   __restrict__ mask,        // [B, T]
    const float* __restrict__ trans,       // [C, C]
    const float* __restrict__ startt,      // [C]
    const float* __restrict__ endt,        // [C]
    float*       __restrict__ out)         // [1]
{
    // Per-warp double-buffered bf16 state: entry i = bf16x2(v[i], v[i]).
    __shared__ __align__(16) u32    pbuf[8][2][NC];
    __shared__ __align__(8)  float2 bbuf[PAIRS][32];   // beta_255 (f32)
    __shared__ float s_logZb[PAIRS];
    __shared__ float s_numb[PAIRS];
    __shared__ bool  s_last;

    const int wid  = threadIdx.x >> 5;
    const int lane = threadIdx.x & 31;
    const int pair = wid >> 1;
    const int role = wid & 1;                 // 0 = forward, 1 = backward
    const int b    = blockIdx.x * PAIRS + pair;
    const int j0   = lane * 2;

    const float* em = emissions + (size_t)b * NT * NC;
    const int*   tg = tags + (size_t)b * NT;
    const int*   mk = mask + (size_t)b * NT;

    float2 et2 = *(const float2*)(endt + j0);

    __nv_bfloat162 e2[NC];
    __nv_bfloat162 pp;          // packed state (this lane's two components)
    int   cur = 0;
    float logZ;

    if (role == 0) {
        // ========================= FORWARD (t = 0..255) =========================
        float2 em0  = *(const float2*)(em + j0);
        float2 emP0 = *(const float2*)(em + (size_t)1 * NC + j0);
        float2 emP1 = *(const float2*)(em + (size_t)2 * NC + j0);
        float2 emP2 = *(const float2*)(em + (size_t)3 * NC + j0);
        int4   mk03 = *(const int4*)(mk);
        int4   mc   = *(const int4*)(mk + 4);
        float2 emc0 = *(const float2*)(em + (size_t)4 * NC + j0);
        float2 emc1 = *(const float2*)(em + (size_t)5 * NC + j0);
        float2 emc2 = *(const float2*)(em + (size_t)6 * NC + j0);
        float2 emc3 = *(const float2*)(em + (size_t)7 * NC + j0);
        float2 st2  = *(const float2*)(startt + j0);

        // e2 = exp(transitions) columns j0, j0+1 (bf16x2)
#pragma unroll
        for (int i = 0; i < NC; i++) {
            float2 tv = *(const float2*)(trans + i * NC + j0);
            e2[i] = __floats2bfloat162_rn(__expf(tv.x), __expf(tv.y));
        }

        // numerator (f32), first half: start term + t in [1, 256)
        float num = 0.f;
#pragma unroll 2
        for (int t = lane; t < HALF_T; t += 32) {
            int tt = tg[t];
            if (t > 0 && mk[t])
                num += trans[tg[t - 1] * NC + tt] + em[(size_t)t * NC + tt];
        }
#pragma unroll
        for (int o = 16; o > 0; o >>= 1)
            num += __shfl_down_sync(FULLMASK, num, o);
        if (lane == 0) {
            int t0 = tg[0];
            num += startt[t0] + em[t0];
        }

        // init t = 0 (values may be negative -> shfl fmax tree)
        float ax = st2.x + em0.x, ay = st2.y + em0.y;
        float m0 = fmaxf(ax, ay);
#pragma unroll
        for (int o = 16; o > 0; o >>= 1)
            m0 = fmaxf(m0, __shfl_xor_sync(FULLMASK, m0, o));
        logZ = m0;
        pp = __floats2bfloat162_rn(__expf(ax - m0), __expf(ay - m0));
        STORE_DUP(pbuf[wid][0], pp);
        __syncwarp();

        STEP_F(emP0, mk03.y, false);
        STEP_F(emP1, mk03.z, false);
        STEP_F(emP2, mk03.w, true);

#pragma unroll 1
        for (int t0 = 4; t0 < HALF_T; t0 += 4) {
            float2 en0 = emc0, en1 = emc1, en2 = emc2, en3 = emc3;
            int4   mn  = mc;
            if (t0 + 4 < HALF_T) {
                const float* p4 = em + (size_t)(t0 + 4) * NC + j0;
                en0 = *(const float2*)(p4);
                en1 = *(const float2*)(p4 + NC);
                en2 = *(const float2*)(p4 + 2 * NC);
                en3 = *(const float2*)(p4 + 3 * NC);
                mn  = *(const int4*)(mk + t0 + 4);
            }
            STEP_F(emc0, mc.x, false);
            STEP_F(emc1, mc.y, false);
            STEP_F(emc2, mc.z, false);
            STEP_F(emc3, mc.w, true);
            emc0 = en0; emc1 = en1; emc2 = en2; emc3 = en3; mc = mn;
        }

        __syncthreads();   // beta_255, logZb, num_b published by bw warp

        float2 pf = __bfloat1622float2(pp);
        float2 bb = bbuf[pair][lane];
        float contrib = pf.x * bb.x + pf.y * bb.y;
#pragma unroll
        for (int o = 16; o > 0; o >>= 1)
            contrib += __shfl_down_sync(FULLMASK, contrib, o);
        if (lane == 0)
            g_partial[b] = logZ + s_logZb[pair] + __logf(contrib)
                           - (num + s_numb[pair]);
    } else {
        // ========================= BACKWARD (t = 511..256) ======================
        float2 emI  = *(const float2*)(em + (size_t)511 * NC + j0);  // e_511
        float2 eP0  = *(const float2*)(em + (size_t)510 * NC + j0);
        float2 eP1  = *(const float2*)(em + (size_t)509 * NC + j0);
        float2 eP2  = *(const float2*)(em + (size_t)508 * NC + j0);
        int mk511 = mk[511], mk510 = mk[510], mk509 = mk[509];
        float2 be0 = *(const float2*)(em + (size_t)507 * NC + j0);
        float2 be1 = *(const float2*)(em + (size_t)506 * NC + j0);
        float2 be2 = *(const float2*)(em + (size_t)505 * NC + j0);
        float2 be3 = *(const float2*)(em + (size_t)504 * NC + j0);
        int m0g = mk[508], m1g = mk[507], m2g = mk[506], m3g = mk[505];
        int mk256 = mk[256];

        // e2 = exp(transitions) ROWS j0, j0+1 (E, not E^T) (bf16x2)
#pragma unroll
        for (int k = 0; k < NC; k++) {
            float tv0 = trans[j0 * NC + k];
            float tv1 = trans[(j0 + 1) * NC + k];
            e2[k] = __floats2bfloat162_rn(__expf(tv0), __expf(tv1));
        }

        // numerator (f32), second half + end term (needs full cnt)
        float num = 0.f;
        int   cnt = 0;
#pragma unroll 2
        for (int t = lane; t < NT; t += 32) {
            int m = mk[t];
            cnt += m;
            if (t >= HALF_T && m) {
                int tt = tg[t];
                num += trans[tg[t - 1] * NC + tt] + em[(size_t)t * NC + tt];
            }
        }
        cnt = __reduce_add_sync(FULLMASK, cnt);
#pragma unroll
        for (int o = 16; o > 0; o >>= 1)
            num += __shfl_down_sync(FULLMASK, num, o);
        if (lane == 0)
            s_numb[pair] = num + endt[tg[cnt - 1]];

        // init: beta_511 = exp(end); store v_511 = e_511 * beta_511
        logZ = 0.f;
        pp = __floats2bfloat162_rn(__expf(et2.x), __expf(et2.y));
        {
            __nv_bfloat162 eI =
                __floats2bfloat162_rn(__expf(emI.x), __expf(emI.y));
            __nv_bfloat162 w = __hmul2(pp, eI);
            STORE_DUP(pbuf[wid][0], w);
        }
        __syncwarp();

        STEP_B(eP0, mk511, false);
        STEP_B(eP1, mk510, false);
        STEP_B(eP2, mk509, true);

#pragma unroll 1
        for (int u0 = 508; u0 >= 260; u0 -= 4) {
            float2 bn0 = be0, bn1 = be1, bn2 = be2, bn3 = be3;
            int n0 = m0g, n1 = m1g, n2 = m2g, n3 = m3g;
            if (u0 > 260) {
                const int u1 = u0 - 4;
                const float* p4 = em + (size_t)(u1 - 4) * NC + j0;
                bn0 = *(const float2*)(p4 + 3 * NC);   // e_{u1-1}
                bn1 = *(const float2*)(p4 + 2 * NC);   // e_{u1-2}
                bn2 = *(const float2*)(p4 + NC);       // e_{u1-3}
                bn3 = *(const float2*)(p4);            // e_{u1-4}
                n0 = mk[u1]; n1 = mk[u1 - 1]; n2 = mk[u1 - 2]; n3 = mk[u1 - 3];
            }
            STEP_B(be0, m0g, false);
            STEP_B(be1, m1g, false);
            STEP_B(be2, m2g, false);
            STEP_B(be3, m3g, true);
            be0 = bn0; be1 = bn1; be2 = bn2; be3 = bn3;
            m0g = n0; m1g = n1; m2g = n2; m3g = n3;
        }

        // final step u = 256: select only (no emission, no store)
        {
            __nv_bfloat162 q_;
            GEMV64H(pbuf[wid][cur], q_);
            if (mk256) pp = q_;
        }
        bbuf[pair][lane] = __bfloat1622float2(pp);
        if (lane == 0) s_logZb[pair] = logZ;

        __syncthreads();   // matches fw warp's barrier
    }

    // ---- fused final reduction: last CTA to finish reduces all 512 ----
    __syncthreads();
    if (threadIdx.x == 0) {
        __threadfence();
        unsigned prev = atomicAdd(&g_done, 1u);
        s_last = (prev == gridDim.x - 1);
    }
    __syncthreads();
    if (s_last && wid == 0) {
        __threadfence();
        float s = 0.f;
        const float4* gp = (const float4*)g_partial;
#pragma unroll
        for (int k = 0; k < 4; k++) {
            float4 v = __ldcg(gp + lane + 32 * k);
            s += (v.x + v.y) + (v.z + v.w);
        }
#pragma unroll
        for (int o = 16; o > 0; o >>= 1)
            s += __shfl_down_sync(FULLMASK, s, o);
        if (lane == 0) {
            out[0] = s * (1.0f / (float)NB);
            g_done = 0;   // reset for next graph replay (deterministic)
        }
    }
}

extern "C" void kernel_launch(void* const* d_in, const int* in_sizes, int n_in,
                              void* d_out, int out_size) {
    const float* emissions = (const float*)d_in[0];
    const int*   tags      = (const int*)d_in[1];
    const int*   mask      = (const int*)d_in[2];
    const float* trans     = (const float*)d_in[3];
    const float* startt    = (const float*)d_in[4];
    const float* endt      = (const float*)d_in[5];
    (void)in_sizes; (void)n_in; (void)out_size;

    crf_forward<<<NB / PAIRS, THREADS>>>(emissions, tags, mask, trans, startt,
                                         endt, (float*)d_out);
}

// round 13
// speedup vs baseline: 4.1626x; 1.1133x over previous
#include <cuda_runtime.h>
#include <cuda_bf16.h>
#include <cstdint>

typedef unsigned long long ull;
typedef unsigned int u32;

#define NB 512
#define NT 512
#define NC 64
#define HALF_T 256        // fw owns t in [0,256); bw owns [256,512)
#define PAIRS 4           // batches per CTA
#define THREADS 256       // 8 warps = 4 (fw,bw) pairs
#define FULLMASK 0xffffffffu
#define LN2F 0.6931471805599453f

__device__ float    g_partial[NB];
__device__ unsigned g_done;

static __device__ __forceinline__ __nv_bfloat162 u2b(u32 u) {
    __nv_bfloat162 r; *reinterpret_cast<u32*>(&r) = u; return r;
}
static __device__ __forceinline__ u32 b2u(__nv_bfloat162 b) {
    return *reinterpret_cast<u32*>(&b);
}

// 64-wide GEMV, packed-pair layout. Buffer entry j = bf16x2(v_2j, v_2j+1)
// (128 B total -> 8x LDS.128 per lane). e2c0[k] = (E[2k][c0], E[2k+1][c0]),
// e2c1 likewise for column c1. Both halves of each accumulator are partial
// sums of the SAME output column; fold once at the end in f32.
#define GEMV64P(SRC, QX, QY) do {                                                \
    const uint4* pb_ = (const uint4*)(SRC);                                      \
    __nv_bfloat162 a0_ = u2b(0u), a1_ = u2b(0u);                                 \
    __nv_bfloat162 c0_ = u2b(0u), c1_ = u2b(0u);                                 \
    _Pragma("unroll")                                                            \
    for (int k_ = 0; k_ < 8; k_++) {                                             \
        uint4 v_ = pb_[k_];                                                      \
        a0_ = __hfma2(u2b(v_.x), e2c0[4 * k_ + 0], a0_);                         \
        c0_ = __hfma2(u2b(v_.x), e2c1[4 * k_ + 0], c0_);                         \
        a1_ = __hfma2(u2b(v_.y), e2c0[4 * k_ + 1], a1_);                         \
        c1_ = __hfma2(u2b(v_.y), e2c1[4 * k_ + 1], c1_);                         \
        a0_ = __hfma2(u2b(v_.z), e2c0[4 * k_ + 2], a0_);                         \
        c0_ = __hfma2(u2b(v_.z), e2c1[4 * k_ + 2], c0_);                         \
        a1_ = __hfma2(u2b(v_.w), e2c0[4 * k_ + 3], a1_);                         \
        c1_ = __hfma2(u2b(v_.w), e2c1[4 * k_ + 3], c1_);                         \
    }                                                                            \
    float2 fa_ = __bfloat1622float2(__hadd2(a0_, a1_));                          \
    float2 fc_ = __bfloat1622float2(__hadd2(c0_, c1_));                          \
    QX = fa_.x + fa_.y;                                                          \
    QY = fc_.x + fc_.y;                                                          \
} while (0)

// Exact power-of-2 renorm of f32 (px,py); p strictly positive.
#define RENORM2() do {                                                           \
    int mb_ = __reduce_max_sync(FULLMASK, __float_as_int(fmaxf(px, py)));        \
    int e_  = mb_ >> 23;                                                         \
    float inv_ = __int_as_float((254 - e_) << 23);   /* 2^(127-e), exact */      \
    px *= inv_; py *= inv_;                                                      \
    logZ += (float)(e_ - 127) * LN2F;                                            \
} while (0)

// Forward step: q = E^T p; masked: p = q * exp(emit_t). Store packed bf16x2.
#define STEP_F(EM, M, REN) do {                                                  \
    float ex_ = __expf((EM).x), ey_ = __expf((EM).y);                            \
    float qx_, qy_; GEMV64P(pbuf[wid][cur], qx_, qy_);                           \
    if (M) { px = qx_ * ex_; py = qy_ * ey_; }                                   \
    if (REN) RENORM2();                                                          \
    cur ^= 1;                                                                    \
    pbuf[wid][cur][lane] = b2u(__floats2bfloat162_rn(px, py));                   \
    __syncwarp();                                                                \
} while (0)

// Backward step: c = E v; masked: beta = c; store v' = beta * exp(emit_{u-1}).
#define STEP_B(EM, M, REN) do {                                                  \
    float ex_ = __expf((EM).x), ey_ = __expf((EM).y);                            \
    float qx_, qy_; GEMV64P(pbuf[wid][cur], qx_, qy_);                           \
    if (M) { px = qx_; py = qy_; }                                               \
    if (REN) RENORM2();                                                          \
    cur ^= 1;                                                                    \
    pbuf[wid][cur][lane] =                                                       \
        b2u(__floats2bfloat162_rn(px * ex_, py * ey_));                          \
    __syncwarp();                                                                \
} while (0)

__global__ void __launch_bounds__(THREADS, 1) crf_forward(
    const float* __restrict__ emissions,   // [B, T, C]
    const int*   __restrict__ tags,        // [B, T]
    const int*   __restrict__ mask,        // [B, T]
    const float* __restrict__ trans,       // [C, C]
    const float* __restrict__ startt,      // [C]
    const float* __restrict__ endt,        // [C]
    float*       __restrict__ out)         // [1]
{
    // Per-warp double-buffered packed bf16 state: entry j = (v_2j, v_2j+1).
    __shared__ __align__(16) u32    pbuf[8][2][32];
    __shared__ __align__(8)  float2 bbuf[PAIRS][32];   // beta_255 (f32)
    __shared__ float s_logZb[PAIRS];
    __shared__ float s_numb[PAIRS];
    __shared__ bool  s_last;

    const int wid  = threadIdx.x >> 5;
    const int lane = threadIdx.x & 31;
    const int pair = wid >> 1;
    const int role = wid & 1;                 // 0 = forward, 1 = backward
    const int b    = blockIdx.x * PAIRS + pair;
    const int j0   = lane * 2;

    const float* em = emissions + (size_t)b * NT * NC;
    const int*   tg = tags + (size_t)b * NT;
    const int*   mk = mask + (size_t)b * NT;

    float2 et2 = *(const float2*)(endt + j0);

    __nv_bfloat162 e2c0[32], e2c1[32];
    int   cur = 0;
    float px, py, logZ;

    if (role == 0) {
        // ========================= FORWARD (t = 0..255) =========================
        float2 em0  = *(const float2*)(em + j0);
        float2 emP0 = *(const float2*)(em + (size_t)1 * NC + j0);
        float2 emP1 = *(const float2*)(em + (size_t)2 * NC + j0);
        float2 emP2 = *(const float2*)(em + (size_t)3 * NC + j0);
        int4   mk03 = *(const int4*)(mk);
        int4   mc   = *(const int4*)(mk + 4);
        float2 emc0 = *(const float2*)(em + (size_t)4 * NC + j0);
        float2 emc1 = *(const float2*)(em + (size_t)5 * NC + j0);
        float2 emc2 = *(const float2*)(em + (size_t)6 * NC + j0);
        float2 emc3 = *(const float2*)(em + (size_t)7 * NC + j0);
        float2 st2  = *(const float2*)(startt + j0);

        // e2c0[k] = (exp T[2k][c0], exp T[2k+1][c0]); e2c1 likewise for c1.
#pragma unroll
        for (int k = 0; k < 32; k++) {
            float2 r0 = *(const float2*)(trans + (2 * k) * NC + j0);
            float2 r1 = *(const float2*)(trans + (2 * k + 1) * NC + j0);
            e2c0[k] = __floats2bfloat162_rn(__expf(r0.x), __expf(r1.x));
            e2c1[k] = __floats2bfloat162_rn(__expf(r0.y), __expf(r1.y));
        }

        // numerator (f32), first half: start term + t in [1, 256)
        float num = 0.f;
#pragma unroll 2
        for (int t = lane; t < HALF_T; t += 32) {
            int tt = tg[t];
            if (t > 0 && mk[t])
                num += trans[tg[t - 1] * NC + tt] + em[(size_t)t * NC + tt];
        }
#pragma unroll
        for (int o = 16; o > 0; o >>= 1)
            num += __shfl_down_sync(FULLMASK, num, o);
        if (lane == 0) {
            int t0 = tg[0];
            num += startt[t0] + em[t0];
        }

        // init t = 0 (values may be negative -> shfl fmax tree)
        float ax = st2.x + em0.x, ay = st2.y + em0.y;
        float m0 = fmaxf(ax, ay);
#pragma unroll
        for (int o = 16; o > 0; o >>= 1)
            m0 = fmaxf(m0, __shfl_xor_sync(FULLMASK, m0, o));
        logZ = m0;
        px = __expf(ax - m0);
        py = __expf(ay - m0);
        pbuf[wid][0][lane] = b2u(__floats2bfloat162_rn(px, py));
        __syncwarp();

        STEP_F(emP0, mk03.y, false);
        STEP_F(emP1, mk03.z, false);
        STEP_F(emP2, mk03.w, true);

#pragma unroll 1
        for (int t0 = 4; t0 < HALF_T; t0 += 4) {
            float2 en0 = emc0, en1 = emc1, en2 = emc2, en3 = emc3;
            int4   mn  = mc;
            if (t0 + 4 < HALF_T) {
                const float* p4 = em + (size_t)(t0 + 4) * NC + j0;
                en0 = *(const float2*)(p4);
                en1 = *(const float2*)(p4 + NC);
                en2 = *(const float2*)(p4 + 2 * NC);
                en3 = *(const float2*)(p4 + 3 * NC);
                mn  = *(const int4*)(mk + t0 + 4);
            }
            STEP_F(emc0, mc.x, false);
            STEP_F(emc1, mc.y, false);
            STEP_F(emc2, mc.z, false);
            STEP_F(emc3, mc.w, true);
            emc0 = en0; emc1 = en1; emc2 = en2; emc3 = en3; mc = mn;
        }

        __syncthreads();   // beta_255, logZb, num_b published by bw warp

        float2 bb = bbuf[pair][lane];
        float contrib = px * bb.x + py * bb.y;
#pragma unroll
        for (int o = 16; o > 0; o >>= 1)
            contrib += __shfl_down_sync(FULLMASK, contrib, o);
        if (lane == 0)
            g_partial[b] = logZ + s_logZb[pair] + __logf(contrib)
                           - (num + s_numb[pair]);
    } else {
        // ========================= BACKWARD (t = 511..256) ======================
        float2 emI  = *(const float2*)(em + (size_t)511 * NC + j0);  // e_511
        float2 eP0  = *(const float2*)(em + (size_t)510 * NC + j0);
        float2 eP1  = *(const float2*)(em + (size_t)509 * NC + j0);
        float2 eP2  = *(const float2*)(em + (size_t)508 * NC + j0);
        int mk511 = mk[511], mk510 = mk[510], mk509 = mk[509];
        float2 be0 = *(const float2*)(em + (size_t)507 * NC + j0);
        float2 be1 = *(const float2*)(em + (size_t)506 * NC + j0);
        float2 be2 = *(const float2*)(em + (size_t)505 * NC + j0);
        float2 be3 = *(const float2*)(em + (size_t)504 * NC + j0);
        int m0g = mk[508], m1g = mk[507], m2g = mk[506], m3g = mk[505];
        int mk256 = mk[256];

        // Backward GEMV: q_c = sum_k E[c][k] v_k.
        // e2c0[k] = (exp T[c0][2k], exp T[c0][2k+1]); e2c1 for row c1.
#pragma unroll
        for (int k = 0; k < 32; k++) {
            float2 r0 = *(const float2*)(trans + j0 * NC + 2 * k);
            float2 r1 = *(const float2*)(trans + (j0 + 1) * NC + 2 * k);
            e2c0[k] = __floats2bfloat162_rn(__expf(r0.x), __expf(r0.y));
            e2c1[k] = __floats2bfloat162_rn(__expf(r1.x), __expf(r1.y));
        }

        // numerator (f32), second half + end term (needs full cnt)
        float num = 0.f;
        int   cnt = 0;
#pragma unroll 2
        for (int t = lane; t < NT; t += 32) {
            int m = mk[t];
            cnt += m;
            if (t >= HALF_T && m) {
                int tt = tg[t];
                num += trans[tg[t - 1] * NC + tt] + em[(size_t)t * NC + tt];
            }
        }
        cnt = __reduce_add_sync(FULLMASK, cnt);
#pragma unroll
        for (int o = 16; o > 0; o >>= 1)
            num += __shfl_down_sync(FULLMASK, num, o);
        if (lane == 0)
            s_numb[pair] = num + endt[tg[cnt - 1]];

        // init: beta_511 = exp(end); store v_511 = e_511 * beta_511
        logZ = 0.f;
        px = __expf(et2.x);
        py = __expf(et2.y);
        pbuf[wid][0][lane] = b2u(__floats2bfloat162_rn(
            px * __expf(emI.x), py * __expf(emI.y)));
        __syncwarp();

        STEP_B(eP0, mk511, false);
        STEP_B(eP1, mk510, false);
        STEP_B(eP2, mk509, true);

#pragma unroll 1
        for (int u0 = 508; u0 >= 260; u0 -= 4) {
            float2 bn0 = be0, bn1 = be1, bn2 = be2, bn3 = be3;
            int n0 = m0g, n1 = m1g, n2 = m2g, n3 = m3g;
            if (u0 > 260) {
                const int u1 = u0 - 4;
                const float* p4 = em + (size_t)(u1 - 4) * NC + j0;
                bn0 = *(const float2*)(p4 + 3 * NC);   // e_{u1-1}
                bn1 = *(const float2*)(p4 + 2 * NC);   // e_{u1-2}
                bn2 = *(const float2*)(p4 + NC);       // e_{u1-3}
                bn3 = *(const float2*)(p4);            // e_{u1-4}
                n0 = mk[u1]; n1 = mk[u1 - 1]; n2 = mk[u1 - 2]; n3 = mk[u1 - 3];
            }
            STEP_B(be0, m0g, false);
            STEP_B(be1, m1g, false);
            STEP_B(be2, m2g, false);
            STEP_B(be3, m3g, true);
            be0 = bn0; be1 = bn1; be2 = bn2; be3 = bn3;
            m0g = n0; m1g = n1; m2g = n2; m3g = n3;
        }

        // final step u = 256: select only (no emission, no store)
        {
            float qx_, qy_;
            GEMV64P(pbuf[wid][cur], qx_, qy_);
            if (mk256) { px = qx_; py = qy_; }
        }
        bbuf[pair][lane] = make_float2(px, py);
        if (lane == 0) s_logZb[pair] = logZ;

        __syncthreads();   // matches fw warp's barrier
    }

    // ---- fused final reduction: last CTA to finish reduces all 512 ----
    __syncthreads();
    if (threadIdx.x == 0) {
        __threadfence();
        unsigned prev = atomicAdd(&g_done, 1u);
        s_last = (prev == gridDim.x - 1);
    }
    __syncthreads();
    if (s_last && wid == 0) {
        __threadfence();
        float s = 0.f;
        const float4* gp = (const float4*)g_partial;
#pragma unroll
        for (int k = 0; k < 4; k++) {
            float4 v = __ldcg(gp + lane + 32 * k);
            s += (v.x + v.y) + (v.z + v.w);
        }
#pragma unroll
        for (int o = 16; o > 0; o >>= 1)
            s += __shfl_down_sync(FULLMASK, s, o);
        if (lane == 0) {
            out[0] = s * (1.0f / (float)NB);
            g_done = 0;   // reset for next graph replay (deterministic)
        }
    }
}

extern "C" void kernel_launch(void* const* d_in, const int* in_sizes, int n_in,
                              void* d_out, int out_size) {
    const float* emissions = (const float*)d_in[0];
    const int*   tags      = (const int*)d_in[1];
    const int*   mask      = (const int*)d_in[2];
    const float* trans     = (const float*)d_in[3];
    const float* startt    = (const float*)d_in[4];
    const float* endt      = (const float*)d_in[5];
    (void)in_sizes; (void)n_in; (void)out_size;

    crf_forward<<<NB / PAIRS, THREADS>>>(emissions, tags, mask, trans, startt,
                                         endt, (float*)d_out);
}